// round 13
// baseline (speedup 1.0000x reference)
#include <cuda_runtime.h>
#include <cuda_fp16.h>
#include <math.h>
#include <stdint.h>

#define N_INST 512
#define L      512
#define VOCAB  50000
#define EMB    128
#define NF     128
#define HID    384
#define ATT    128
#define NCLS   53
#define NHB    32          // h_bag partial blocks

// ---------------- scratch (static device globals; no runtime alloc) ---------
__device__ __half g_Bf[HID * EMB];                  // [c][e] fp16, c = kt*128+f
__device__ __half g_Wth[HID * ATT];                 // Ww transposed fp16: [h][a]
__device__ __half g_projh[(size_t)VOCAB * HID];     // [v][c] fp16
__device__ float g_H[N_INST * HID];
__device__ float g_scores[N_INST];
__device__ float g_hbp[NHB * HID];                  // h_bag partials

// ---------------- prep: B transpose (fp16) + Ww transpose (fp16) -----------
__global__ void k_prep(const float* __restrict__ conv_w, const float* __restrict__ Ww) {
    int idx = blockIdx.x * blockDim.x + threadIdx.x;
    if (idx < HID * EMB) {
        int c = idx >> 7, e = idx & 127;
        int f = c & 127, kt = c >> 7;
        g_Bf[c * EMB + e] = __float2half(conv_w[(f * EMB + e) * 3 + kt]);
    } else if (idx < 2 * HID * EMB) {
        int j = idx - HID * EMB;            // j = h*128 + a
        int h = j >> 7, a = j & 127;
        g_Wth[j] = __float2half(Ww[a * HID + h]);
    }
}

// ---------------- K1: fp16-acc mma.sync proj GEMM, single A pass -----------
#define SROW 136                      // padded half row stride (272 B)
#define K1_SMEM (2 * 128 * SROW * 2)  // 69632 B -> 3 CTAs/SM

#define MMA_F16ACC(d, a, b) \
    asm volatile("mma.sync.aligned.m16n8k16.row.col.f16.f16.f16.f16 " \
        "{%0,%1}, {%2,%3,%4,%5}, {%6,%7}, {%0,%1};" \
        : "+r"(d[0]), "+r"(d[1]) \
        : "r"(a[0]), "r"(a[1]), "r"(a[2]), "r"(a[3]), "r"(b[0]), "r"(b[1]))

__global__ __launch_bounds__(256, 3) void k1_hmma(const float* __restrict__ emb) {
    extern __shared__ __half sm_[];
    __half* As = sm_;
    __half* Bs = sm_ + 128 * SROW;     // doubles as C staging after compute

    int tid = threadIdx.x;
    int m0 = blockIdx.x * 128;

    for (int i = tid; i < 2048; i += 256) {          // 128 rows x 16 chunks of 8
        int row = i >> 4, k = (i & 15) * 8;
        int gm = m0 + row;
        uint2 p0 = make_uint2(0u, 0u), p1 = make_uint2(0u, 0u);
        if (gm < VOCAB) {
            float4 f0 = *(const float4*)&emb[(size_t)gm * EMB + k];
            float4 f1 = *(const float4*)&emb[(size_t)gm * EMB + k + 4];
            __half2 h0 = __floats2half2_rn(f0.x, f0.y);
            __half2 h1 = __floats2half2_rn(f0.z, f0.w);
            __half2 h2 = __floats2half2_rn(f1.x, f1.y);
            __half2 h3 = __floats2half2_rn(f1.z, f1.w);
            p0 = make_uint2(*(uint32_t*)&h0, *(uint32_t*)&h1);
            p1 = make_uint2(*(uint32_t*)&h2, *(uint32_t*)&h3);
        }
        *(uint2*)&As[row * SROW + k]     = p0;
        *(uint2*)&As[row * SROW + k + 4] = p1;
    }

    int lane = tid & 31, g = lane >> 2, t = lane & 3;
    int wid = tid >> 5;
    int mbase = (wid & 3) * 32;
    int nbase = (wid >> 2) * 64;

    for (int nb = 0; nb < 3; nb++) {
        for (int i = tid; i < 2048; i += 256) {
            int row = i >> 4, k = (i & 15) * 8;
            *(int4*)&Bs[row * SROW + k] =
                *(const int4*)&g_Bf[(nb * 128 + row) * EMB + k];
        }
        __syncthreads();

        uint32_t acc[2][8][2];
#pragma unroll
        for (int mi = 0; mi < 2; mi++)
#pragma unroll
            for (int nj = 0; nj < 8; nj++) { acc[mi][nj][0] = 0u; acc[mi][nj][1] = 0u; }

#pragma unroll
        for (int ks = 0; ks < 8; ks++) {
            int k16 = ks * 16;
            uint32_t a[2][4], b[8][2];
#pragma unroll
            for (int mi = 0; mi < 2; mi++) {
                int r0 = mbase + mi * 16 + g;
                a[mi][0] = *(const uint32_t*)&As[r0 * SROW + k16 + t * 2];
                a[mi][1] = *(const uint32_t*)&As[(r0 + 8) * SROW + k16 + t * 2];
                a[mi][2] = *(const uint32_t*)&As[r0 * SROW + k16 + 8 + t * 2];
                a[mi][3] = *(const uint32_t*)&As[(r0 + 8) * SROW + k16 + 8 + t * 2];
            }
#pragma unroll
            for (int nj = 0; nj < 8; nj++) {
                int n0i = nbase + nj * 8 + g;
                b[nj][0] = *(const uint32_t*)&Bs[n0i * SROW + k16 + t * 2];
                b[nj][1] = *(const uint32_t*)&Bs[n0i * SROW + k16 + 8 + t * 2];
            }
#pragma unroll
            for (int mi = 0; mi < 2; mi++)
#pragma unroll
                for (int nj = 0; nj < 8; nj++) MMA_F16ACC(acc[mi][nj], a[mi], b[nj]);
        }
        __syncthreads();

#pragma unroll
        for (int mi = 0; mi < 2; mi++)
#pragma unroll
            for (int nj = 0; nj < 8; nj++) {
                int r = mbase + mi * 16 + g;
                int cc = nbase + nj * 8 + t * 2;
                *(uint32_t*)&Bs[r * SROW + cc]       = acc[mi][nj][0];
                *(uint32_t*)&Bs[(r + 8) * SROW + cc] = acc[mi][nj][1];
            }
        __syncthreads();
        {
            int row = tid >> 1, seg = tid & 1;
            int gm = m0 + row;
            if (gm < VOCAB) {
                const int4* src = (const int4*)&Bs[row * SROW + seg * 64];
                int4* dst = (int4*)&g_projh[(size_t)gm * HID + nb * 128 + seg * 64];
#pragma unroll
                for (int j = 0; j < 8; j++) dst[j] = src[j];
            }
        }
        __syncthreads();
    }
}

// ---------------- K2: gather + pool + fused scores (fp16 Wt) ---------------
// 512 blocks x 512 threads, 1 instance/block. Score phase: thread =
// (ap = tid&63 -> a-pair, hg = tid>>6 -> 48 h), half2 Wt loads (48 LDG/thr).
__global__ __launch_bounds__(512) void k2_pool(const int* __restrict__ ids_g,
                                               const int* __restrict__ pe1,
                                               const int* __restrict__ pe2,
                                               const float* __restrict__ conv_b,
                                               const float* __restrict__ Wb,
                                               const float* __restrict__ u) {
    int n = blockIdx.x;
    int tid = threadIdx.x;
    int f4 = tid & 31, part = tid >> 5;
    __shared__ int S[L + 2];
    __shared__ uint2 pb[3][16][32];
    __shared__ __align__(16) float Hsm[HID];
    __shared__ __align__(16) float partial2[8][128];
    __shared__ float red[4];

    for (int i = tid; i < L; i += 512) S[i + 1] = ids_g[n * L + i] * (HID * 2);
    if (tid == 0) { S[0] = 0; S[L + 1] = 0; }
    __syncthreads();

    int p1 = pe1[n], p2 = pe2[n];
    int e1 = min(p1, p2), e2 = max(p1, p2);
    e1 = max(0, min(e1, L));
    e2 = max(0, min(e2, L));
    if (e1 == e2) e2 = min(e1 + 1, L);
    int end1 = (e1 > 0) ? e1 : 1;

    __half2 hb0 = __floats2half2_rn(conv_b[4 * f4], conv_b[4 * f4 + 1]);
    __half2 hb1 = __floats2half2_rn(conv_b[4 * f4 + 2], conv_b[4 * f4 + 3]);
    __half2 zz = __floats2half2_rn(0.f, 0.f);
    __half2 m10 = zz, m11 = zz, m20 = zz, m21 = zz, m30 = zz, m31 = zz;

    const char* base = (const char*)g_projh;
    int coff = f4 * 8;
    int t0 = part * 32;

#pragma unroll 4
    for (int l = t0; l < t0 + 32; l++) {
        uint2 v0 = *(const uint2*)(base + S[l] + coff);
        uint2 v1 = *(const uint2*)(base + S[l + 1] + 256 + coff);
        uint2 v2 = *(const uint2*)(base + S[l + 2] + 512 + coff);
        __half2 s0 = __hadd2(__hadd2(*(__half2*)&v0.x, *(__half2*)&v1.x),
                             __hadd2(*(__half2*)&v2.x, hb0));
        __half2 s1 = __hadd2(__hadd2(*(__half2*)&v0.y, *(__half2*)&v1.y),
                             __hadd2(*(__half2*)&v2.y, hb1));
        if (l < end1)          { m10 = __hmax2(m10, s0); m11 = __hmax2(m11, s1); }
        if (l >= e1 && l < e2) { m20 = __hmax2(m20, s0); m21 = __hmax2(m21, s1); }
        bool in3 = (e2 < L) ? (l >= e2) : (l == L - 1);
        if (in3)               { m30 = __hmax2(m30, s0); m31 = __hmax2(m31, s1); }
    }
    pb[0][part][f4] = make_uint2(*(uint32_t*)&m10, *(uint32_t*)&m11);
    pb[1][part][f4] = make_uint2(*(uint32_t*)&m20, *(uint32_t*)&m21);
    pb[2][part][f4] = make_uint2(*(uint32_t*)&m30, *(uint32_t*)&m31);
    __syncthreads();

    if (tid < 96) {
        int seg = tid >> 5, fm = tid & 31;
        __half2 r0 = zz, r1 = zz;
#pragma unroll
        for (int q = 0; q < 16; q++) {
            uint2 v = pb[seg][q][fm];
            r0 = __hmax2(r0, *(__half2*)&v.x);
            r1 = __hmax2(r1, *(__half2*)&v.y);
        }
        float2 a = __half22float2(r0), bq = __half22float2(r1);
        float4 hv = make_float4(a.x, a.y, bq.x, bq.y);
        *(float4*)&g_H[n * HID + seg * 128 + 4 * fm] = hv;
        *(float4*)&Hsm[seg * 128 + 4 * fm] = hv;
    }
    __syncthreads();

    // ---- fused scores: thread = (ap = tid&63, hg = tid>>6 covers 48 h) ----
    {
        int ap = tid & 63, hg = tid >> 6;
        float acc0 = 0.f, acc1 = 0.f;
        const __half* W = g_Wth + 2 * ap;
        int h0 = hg * 48;
#pragma unroll 8
        for (int h = h0; h < h0 + 48; h++) {
            float2 wv = __half22float2(*(const __half2*)(W + h * ATT));
            float hv = Hsm[h];
            acc0 += hv * wv.x;
            acc1 += hv * wv.y;
        }
        partial2[hg][2 * ap]     = acc0;
        partial2[hg][2 * ap + 1] = acc1;
    }
    __syncthreads();
    if (tid < 128) {
        int a = tid;
        float s = 0.f;
#pragma unroll
        for (int hg = 0; hg < 8; hg++) s += partial2[hg][a];
        float e = tanhf(s + __ldg(&Wb[a])) * __ldg(&u[a]);
#pragma unroll
        for (int off = 16; off; off >>= 1)
            e += __shfl_down_sync(0xffffffffu, e, off);
        if ((tid & 31) == 0) red[tid >> 5] = e;
    }
    __syncthreads();
    if (tid == 0) g_scores[n] = red[0] + red[1] + red[2] + red[3];
}

// ---------------- softmax helper (no max subtraction; |s| <= ~9) -----------
__device__ __forceinline__ float block_softmax_512(int tid, float* attn_s,
                                                   float* red16) {
    float e = expf(g_scores[tid]);
    float sv = e;
#pragma unroll
    for (int off = 16; off; off >>= 1)
        sv += __shfl_xor_sync(0xffffffffu, sv, off);
    if ((tid & 31) == 0) red16[tid >> 5] = sv;
    __syncthreads();
    __shared__ float bsum;
    if (tid == 0) {
        float t = 0.f;
        for (int i = 0; i < 16; i++) t += red16[i];
        bsum = t;
    }
    __syncthreads();
    float a = e / bsum;
    attn_s[tid] = a;
    __syncthreads();
    return a;
}

// ---------------- K4: h_bag partials (32 blocks x 16 instances) ------------
__global__ __launch_bounds__(512) void k4_hbag() {
    int tid = threadIdx.x;
    int b = blockIdx.x;
    __shared__ float attn_s[N_INST];
    __shared__ float red16[16];
    block_softmax_512(tid, attn_s, red16);

    if (tid < HID) {
        int n0 = b * 16;
        float acc = 0.f;
#pragma unroll
        for (int j = 0; j < 16; j++)
            acc += attn_s[n0 + j] * g_H[(n0 + j) * HID + tid];
        g_hbp[b * HID + tid] = acc;
    }
}

// ---------------- K5: attn out + hb sum + logits ---------------------------
__global__ __launch_bounds__(512) void k5_out(const float* __restrict__ fc_w,
                                              const float* __restrict__ fc_b,
                                              float* __restrict__ out) {
    int tid = threadIdx.x;
    __shared__ float attn_s[N_INST];
    __shared__ float red16[16];
    __shared__ float hb[HID];

    float a = block_softmax_512(tid, attn_s, red16);
    out[NCLS + tid] = a;

    if (tid < HID) {
        float acc = 0.f;
#pragma unroll
        for (int b = 0; b < NHB; b++)
            acc += g_hbp[b * HID + tid];
        hb[tid] = acc;
    }
    __syncthreads();

    int w = tid >> 5, lane = tid & 31;
    for (int t = w; t < NCLS; t += 16) {
        float part = 0.f;
#pragma unroll
        for (int c = lane; c < HID; c += 32)
            part += hb[c] * __ldg(&fc_w[t * HID + c]);
#pragma unroll
        for (int off = 16; off; off >>= 1)
            part += __shfl_down_sync(0xffffffffu, part, off);
        if (lane == 0) out[t] = part + fc_b[t];
    }
}

// ---------------- launch ------------------------------------------------------
extern "C" void kernel_launch(void* const* d_in, const int* in_sizes, int n_in,
                              void* d_out, int out_size) {
    const int*   char_ids = (const int*)d_in[0];
    const int*   pe1      = (const int*)d_in[1];
    const int*   pe2      = (const int*)d_in[2];
    const float* emb      = (const float*)d_in[3];
    const float* conv_w   = (const float*)d_in[4];
    const float* conv_b   = (const float*)d_in[5];
    const float* W_w      = (const float*)d_in[6];
    const float* W_b      = (const float*)d_in[7];
    const float* u_w      = (const float*)d_in[8];
    const float* fc_w     = (const float*)d_in[9];
    const float* fc_b     = (const float*)d_in[10];
    float* out = (float*)d_out;

    static bool attr_set = false;
    if (!attr_set) {
        cudaFuncSetAttribute(k1_hmma, cudaFuncAttributeMaxDynamicSharedMemorySize, K1_SMEM);
        attr_set = true;
    }

    k_prep<<<(2 * HID * EMB + 255) / 256, 256>>>(conv_w, W_w);
    k1_hmma<<<(VOCAB + 127) / 128, 256, K1_SMEM>>>(emb);
    k2_pool<<<N_INST, 512>>>(char_ids, pe1, pe2, conv_b, W_b, u_w);
    k4_hbag<<<NHB, 512>>>();
    k5_out<<<1, 512>>>(fc_w, fc_b, out);
}

// round 14
// speedup vs baseline: 1.0049x; 1.0049x over previous
#include <cuda_runtime.h>
#include <cuda_fp16.h>
#include <math.h>
#include <stdint.h>

#define N_INST 512
#define L      512
#define VOCAB  50000
#define EMB    128
#define NF     128
#define HID    384
#define ATT    128
#define NCLS   53
#define NHB    128         // h_bag partial blocks (4 instances each)

// ---------------- scratch (static device globals; no runtime alloc) ---------
__device__ __half g_Bf[HID * EMB];                  // [c][e] fp16, c = kt*128+f
__device__ float  g_Wt[HID * ATT];                  // Ww transposed fp32: [h][a]
__device__ __half g_projh[(size_t)VOCAB * HID];     // [v][c] fp16
__device__ float g_H[N_INST * HID];
__device__ float g_scores[N_INST];
__device__ float g_hbp[NHB * HID];                  // h_bag partials

// ---------------- prep (two launches so ncu's 4th-launch sample = k2) ------
__global__ void k_prep_B(const float* __restrict__ conv_w) {
    int idx = blockIdx.x * blockDim.x + threadIdx.x;
    if (idx >= HID * EMB) return;
    int c = idx >> 7, e = idx & 127;
    int f = c & 127, kt = c >> 7;
    g_Bf[c * EMB + e] = __float2half(conv_w[(f * EMB + e) * 3 + kt]);
}
__global__ void k_prep_W(const float* __restrict__ Ww) {
    int j = blockIdx.x * blockDim.x + threadIdx.x;
    if (j >= HID * ATT) return;
    int h = j >> 7, a = j & 127;
    g_Wt[j] = Ww[a * HID + h];
}

// ---------------- K1: fp16-acc mma.sync proj GEMM, single A pass -----------
#define SROW 136                      // padded half row stride (272 B)
#define K1_SMEM (2 * 128 * SROW * 2)  // 69632 B -> 3 CTAs/SM

#define MMA_F16ACC(d, a, b) \
    asm volatile("mma.sync.aligned.m16n8k16.row.col.f16.f16.f16.f16 " \
        "{%0,%1}, {%2,%3,%4,%5}, {%6,%7}, {%0,%1};" \
        : "+r"(d[0]), "+r"(d[1]) \
        : "r"(a[0]), "r"(a[1]), "r"(a[2]), "r"(a[3]), "r"(b[0]), "r"(b[1]))

__global__ __launch_bounds__(256, 3) void k1_hmma(const float* __restrict__ emb) {
    extern __shared__ __half sm_[];
    __half* As = sm_;
    __half* Bs = sm_ + 128 * SROW;     // doubles as C staging after compute

    int tid = threadIdx.x;
    int m0 = blockIdx.x * 128;

    for (int i = tid; i < 2048; i += 256) {          // 128 rows x 16 chunks of 8
        int row = i >> 4, k = (i & 15) * 8;
        int gm = m0 + row;
        uint2 p0 = make_uint2(0u, 0u), p1 = make_uint2(0u, 0u);
        if (gm < VOCAB) {
            float4 f0 = *(const float4*)&emb[(size_t)gm * EMB + k];
            float4 f1 = *(const float4*)&emb[(size_t)gm * EMB + k + 4];
            __half2 h0 = __floats2half2_rn(f0.x, f0.y);
            __half2 h1 = __floats2half2_rn(f0.z, f0.w);
            __half2 h2 = __floats2half2_rn(f1.x, f1.y);
            __half2 h3 = __floats2half2_rn(f1.z, f1.w);
            p0 = make_uint2(*(uint32_t*)&h0, *(uint32_t*)&h1);
            p1 = make_uint2(*(uint32_t*)&h2, *(uint32_t*)&h3);
        }
        *(uint2*)&As[row * SROW + k]     = p0;
        *(uint2*)&As[row * SROW + k + 4] = p1;
    }

    int lane = tid & 31, g = lane >> 2, t = lane & 3;
    int wid = tid >> 5;
    int mbase = (wid & 3) * 32;
    int nbase = (wid >> 2) * 64;

    for (int nb = 0; nb < 3; nb++) {
        for (int i = tid; i < 2048; i += 256) {
            int row = i >> 4, k = (i & 15) * 8;
            *(int4*)&Bs[row * SROW + k] =
                *(const int4*)&g_Bf[(nb * 128 + row) * EMB + k];
        }
        __syncthreads();

        uint32_t acc[2][8][2];
#pragma unroll
        for (int mi = 0; mi < 2; mi++)
#pragma unroll
            for (int nj = 0; nj < 8; nj++) { acc[mi][nj][0] = 0u; acc[mi][nj][1] = 0u; }

#pragma unroll
        for (int ks = 0; ks < 8; ks++) {
            int k16 = ks * 16;
            uint32_t a[2][4], b[8][2];
#pragma unroll
            for (int mi = 0; mi < 2; mi++) {
                int r0 = mbase + mi * 16 + g;
                a[mi][0] = *(const uint32_t*)&As[r0 * SROW + k16 + t * 2];
                a[mi][1] = *(const uint32_t*)&As[(r0 + 8) * SROW + k16 + t * 2];
                a[mi][2] = *(const uint32_t*)&As[r0 * SROW + k16 + 8 + t * 2];
                a[mi][3] = *(const uint32_t*)&As[(r0 + 8) * SROW + k16 + 8 + t * 2];
            }
#pragma unroll
            for (int nj = 0; nj < 8; nj++) {
                int n0i = nbase + nj * 8 + g;
                b[nj][0] = *(const uint32_t*)&Bs[n0i * SROW + k16 + t * 2];
                b[nj][1] = *(const uint32_t*)&Bs[n0i * SROW + k16 + 8 + t * 2];
            }
#pragma unroll
            for (int mi = 0; mi < 2; mi++)
#pragma unroll
                for (int nj = 0; nj < 8; nj++) MMA_F16ACC(acc[mi][nj], a[mi], b[nj]);
        }
        __syncthreads();

#pragma unroll
        for (int mi = 0; mi < 2; mi++)
#pragma unroll
            for (int nj = 0; nj < 8; nj++) {
                int r = mbase + mi * 16 + g;
                int cc = nbase + nj * 8 + t * 2;
                *(uint32_t*)&Bs[r * SROW + cc]       = acc[mi][nj][0];
                *(uint32_t*)&Bs[(r + 8) * SROW + cc] = acc[mi][nj][1];
            }
        __syncthreads();
        {
            int row = tid >> 1, seg = tid & 1;
            int gm = m0 + row;
            if (gm < VOCAB) {
                const int4* src = (const int4*)&Bs[row * SROW + seg * 64];
                int4* dst = (int4*)&g_projh[(size_t)gm * HID + nb * 128 + seg * 64];
#pragma unroll
                for (int j = 0; j < 8; j++) dst[j] = src[j];
            }
        }
        __syncthreads();
    }
}

// ---------------- K2: gather + pool + fused scores, 2 inst/block -----------
// 256 blocks x 512 threads. Gather: thread = (f8 = tid&15 -> 8 filters via
// LDG.128, part = (tid>>4)&15 -> 32 tokens, inst = tid>>8). Score: each fp32
// Wt load feeds both instances.
__global__ __launch_bounds__(512) void k2_pool(const int* __restrict__ ids_g,
                                               const int* __restrict__ pe1,
                                               const int* __restrict__ pe2,
                                               const float* __restrict__ conv_b,
                                               const float* __restrict__ Wb,
                                               const float* __restrict__ u) {
    int n0 = blockIdx.x * 2;
    int tid = threadIdx.x;
    int f8 = tid & 15, part = (tid >> 4) & 15, inst = tid >> 8;
    __shared__ int S[2][L + 2];
    __shared__ uint4 pb[2][3][16][16];
    __shared__ __align__(16) float Hsm[2][HID];
    __shared__ __align__(16) float partial[2][4][128];
    __shared__ float red[2][4];

    for (int i = tid; i < 2 * L; i += 512) {
        int ii = i >> 9, l = i & 511;
        S[ii][l + 1] = ids_g[(n0 + ii) * L + l] * (HID * 2);
    }
    if (tid < 2) { S[tid][0] = 0; S[tid][L + 1] = 0; }
    __syncthreads();

    int p1 = pe1[n0 + inst], p2 = pe2[n0 + inst];
    int e1 = min(p1, p2), e2 = max(p1, p2);
    e1 = max(0, min(e1, L));
    e2 = max(0, min(e2, L));
    if (e1 == e2) e2 = min(e1 + 1, L);
    int end1 = (e1 > 0) ? e1 : 1;

    __half2 hb[4];
#pragma unroll
    for (int j = 0; j < 4; j++)
        hb[j] = __floats2half2_rn(conv_b[8 * f8 + 2 * j], conv_b[8 * f8 + 2 * j + 1]);
    __half2 zz = __floats2half2_rn(0.f, 0.f);
    __half2 m1[4] = {zz, zz, zz, zz}, m2[4] = {zz, zz, zz, zz}, m3[4] = {zz, zz, zz, zz};

    const char* base = (const char*)g_projh;
    int coff = f8 * 16;
    int t0 = part * 32;
    const int* Si = S[inst];

#pragma unroll 4
    for (int l = t0; l < t0 + 32; l++) {
        uint4 v0 = *(const uint4*)(base + Si[l] + coff);            // tok l-1 tap0
        uint4 v1 = *(const uint4*)(base + Si[l + 1] + 256 + coff);  // tok l   tap1
        uint4 v2 = *(const uint4*)(base + Si[l + 2] + 512 + coff);  // tok l+1 tap2
        __half2 s[4];
        s[0] = __hadd2(__hadd2(*(__half2*)&v0.x, *(__half2*)&v1.x),
                       __hadd2(*(__half2*)&v2.x, hb[0]));
        s[1] = __hadd2(__hadd2(*(__half2*)&v0.y, *(__half2*)&v1.y),
                       __hadd2(*(__half2*)&v2.y, hb[1]));
        s[2] = __hadd2(__hadd2(*(__half2*)&v0.z, *(__half2*)&v1.z),
                       __hadd2(*(__half2*)&v2.z, hb[2]));
        s[3] = __hadd2(__hadd2(*(__half2*)&v0.w, *(__half2*)&v1.w),
                       __hadd2(*(__half2*)&v2.w, hb[3]));
        bool in1 = (l < end1);
        bool in2 = (l >= e1 && l < e2);
        bool in3 = (e2 < L) ? (l >= e2) : (l == L - 1);
#pragma unroll
        for (int j = 0; j < 4; j++) {
            if (in1) m1[j] = __hmax2(m1[j], s[j]);
            if (in2) m2[j] = __hmax2(m2[j], s[j]);
            if (in3) m3[j] = __hmax2(m3[j], s[j]);
        }
    }
    pb[inst][0][part][f8] = make_uint4(*(uint32_t*)&m1[0], *(uint32_t*)&m1[1],
                                       *(uint32_t*)&m1[2], *(uint32_t*)&m1[3]);
    pb[inst][1][part][f8] = make_uint4(*(uint32_t*)&m2[0], *(uint32_t*)&m2[1],
                                       *(uint32_t*)&m2[2], *(uint32_t*)&m2[3]);
    pb[inst][2][part][f8] = make_uint4(*(uint32_t*)&m3[0], *(uint32_t*)&m3[1],
                                       *(uint32_t*)&m3[2], *(uint32_t*)&m3[3]);
    __syncthreads();

    if (tid < 96) {
        int ii = tid / 48, r = tid % 48;
        int seg = r >> 4, fm = r & 15;
        __half2 r0 = zz, r1 = zz, r2 = zz, r3 = zz;
#pragma unroll
        for (int q = 0; q < 16; q++) {
            uint4 v = pb[ii][seg][q][fm];
            r0 = __hmax2(r0, *(__half2*)&v.x);
            r1 = __hmax2(r1, *(__half2*)&v.y);
            r2 = __hmax2(r2, *(__half2*)&v.z);
            r3 = __hmax2(r3, *(__half2*)&v.w);
        }
        float2 a0 = __half22float2(r0), a1 = __half22float2(r1);
        float2 a2 = __half22float2(r2), a3 = __half22float2(r3);
        float4 hv0 = make_float4(a0.x, a0.y, a1.x, a1.y);
        float4 hv1 = make_float4(a2.x, a2.y, a3.x, a3.y);
        int off = seg * 128 + 8 * fm;
        *(float4*)&g_H[(n0 + ii) * HID + off]     = hv0;
        *(float4*)&g_H[(n0 + ii) * HID + off + 4] = hv1;
        *(float4*)&Hsm[ii][off]     = hv0;
        *(float4*)&Hsm[ii][off + 4] = hv1;
    }
    __syncthreads();

    // ---- fused scores: thread = (a = tid&127, hg = tid>>7 covers 96 h) ----
    {
        int a = tid & 127, hg = tid >> 7;
        float acc0 = 0.f, acc1 = 0.f;
        const float* W = g_Wt + a;
        int h0 = hg * 96;
#pragma unroll 8
        for (int h = h0; h < h0 + 96; h++) {
            float wv = __ldg(W + h * ATT);
            acc0 += Hsm[0][h] * wv;
            acc1 += Hsm[1][h] * wv;
        }
        partial[0][hg][a] = acc0;
        partial[1][hg][a] = acc1;
    }
    __syncthreads();
    if (tid < 256) {
        int ii = tid >> 7, a = tid & 127;
        float s = partial[ii][0][a] + partial[ii][1][a] +
                  partial[ii][2][a] + partial[ii][3][a];
        float e = tanhf(s + __ldg(&Wb[a])) * __ldg(&u[a]);
#pragma unroll
        for (int off = 16; off; off >>= 1)
            e += __shfl_down_sync(0xffffffffu, e, off);
        if ((tid & 31) == 0) red[ii][(tid >> 5) & 3] = e;
    }
    __syncthreads();
    if (tid < 2)
        g_scores[n0 + tid] = red[tid][0] + red[tid][1] + red[tid][2] + red[tid][3];
}

// ---------------- softmax helper (no max subtraction; |s| <= ~9) -----------
__device__ __forceinline__ float block_softmax_512(int tid, float* attn_s,
                                                   float* red16) {
    float e = expf(g_scores[tid]);
    float sv = e;
#pragma unroll
    for (int off = 16; off; off >>= 1)
        sv += __shfl_xor_sync(0xffffffffu, sv, off);
    if ((tid & 31) == 0) red16[tid >> 5] = sv;
    __syncthreads();
    __shared__ float bsum;
    if (tid == 0) {
        float t = 0.f;
        for (int i = 0; i < 16; i++) t += red16[i];
        bsum = t;
    }
    __syncthreads();
    float a = e / bsum;
    attn_s[tid] = a;
    __syncthreads();
    return a;
}

// ---------------- K4: h_bag partials (128 blocks x 4 instances) ------------
__global__ __launch_bounds__(512) void k4_hbag() {
    int tid = threadIdx.x;
    int b = blockIdx.x;
    __shared__ float attn_s[N_INST];
    __shared__ float red16[16];
    block_softmax_512(tid, attn_s, red16);

    if (tid < HID) {
        int n0 = b * 4;
        float acc = 0.f;
#pragma unroll
        for (int j = 0; j < 4; j++)
            acc += attn_s[n0 + j] * g_H[(n0 + j) * HID + tid];
        g_hbp[b * HID + tid] = acc;
    }
}

// ---------------- K5: attn out + hb sum + logits ---------------------------
__global__ __launch_bounds__(512) void k5_out(const float* __restrict__ fc_w,
                                              const float* __restrict__ fc_b,
                                              float* __restrict__ out) {
    int tid = threadIdx.x;
    __shared__ float attn_s[N_INST];
    __shared__ float red16[16];
    __shared__ float hb[HID];

    float a = block_softmax_512(tid, attn_s, red16);
    out[NCLS + tid] = a;

    if (tid < HID) {
        float acc = 0.f;
#pragma unroll 16
        for (int b = 0; b < NHB; b++)
            acc += g_hbp[b * HID + tid];
        hb[tid] = acc;
    }
    __syncthreads();

    int w = tid >> 5, lane = tid & 31;
    for (int t = w; t < NCLS; t += 16) {
        float part = 0.f;
#pragma unroll
        for (int c = lane; c < HID; c += 32)
            part += hb[c] * __ldg(&fc_w[t * HID + c]);
#pragma unroll
        for (int off = 16; off; off >>= 1)
            part += __shfl_down_sync(0xffffffffu, part, off);
        if (lane == 0) out[t] = part + fc_b[t];
    }
}

// ---------------- launch ------------------------------------------------------
extern "C" void kernel_launch(void* const* d_in, const int* in_sizes, int n_in,
                              void* d_out, int out_size) {
    const int*   char_ids = (const int*)d_in[0];
    const int*   pe1      = (const int*)d_in[1];
    const int*   pe2      = (const int*)d_in[2];
    const float* emb      = (const float*)d_in[3];
    const float* conv_w   = (const float*)d_in[4];
    const float* conv_b   = (const float*)d_in[5];
    const float* W_w      = (const float*)d_in[6];
    const float* W_b      = (const float*)d_in[7];
    const float* u_w      = (const float*)d_in[8];
    const float* fc_w     = (const float*)d_in[9];
    const float* fc_b     = (const float*)d_in[10];
    float* out = (float*)d_out;

    static bool attr_set = false;
    if (!attr_set) {
        cudaFuncSetAttribute(k1_hmma, cudaFuncAttributeMaxDynamicSharedMemorySize, K1_SMEM);
        attr_set = true;
    }

    k_prep_B<<<(HID * EMB + 255) / 256, 256>>>(conv_w);
    k_prep_W<<<(HID * ATT + 255) / 256, 256>>>(W_w);
    k1_hmma<<<(VOCAB + 127) / 128, 256, K1_SMEM>>>(emb);
    k2_pool<<<N_INST / 2, 512>>>(char_ids, pe1, pe2, conv_b, W_b, u_w);
    k4_hbag<<<NHB, 512>>>();
    k5_out<<<1, 512>>>(fc_w, fc_b, out);
}

// round 15
// speedup vs baseline: 1.0291x; 1.0241x over previous
#include <cuda_runtime.h>
#include <cuda_fp16.h>
#include <math.h>
#include <stdint.h>

#define N_INST 512
#define L      512
#define VOCAB  50000
#define EMB    128
#define NF     128
#define HID    384
#define ATT    128
#define NCLS   53
#define NHB    128         // h_bag partial blocks (4 instances each)

// ---------------- scratch (static device globals; no runtime alloc) ---------
__device__ __half g_Bf[HID * EMB];                  // [c][e] fp16, c = kt*128+f
__device__ float  g_Wt[HID * ATT];                  // Ww transposed fp32: [h][a]
__device__ __half g_projh[(size_t)VOCAB * HID];     // [v][c] fp16
__device__ float g_H[N_INST * HID];
__device__ float g_scores[N_INST];
__device__ float g_hbp[NHB * HID];                  // h_bag partials

// ---------------- prep: B transpose (fp16) + Ww transpose (fp32) -----------
__global__ void k_prep(const float* __restrict__ conv_w, const float* __restrict__ Ww) {
    int idx = blockIdx.x * blockDim.x + threadIdx.x;
    if (idx < HID * EMB) {
        int c = idx >> 7, e = idx & 127;
        int f = c & 127, kt = c >> 7;
        g_Bf[c * EMB + e] = __float2half(conv_w[(f * EMB + e) * 3 + kt]);
    } else if (idx < 2 * HID * EMB) {
        int j = idx - HID * EMB;            // j = h*128 + a
        int h = j >> 7, a = j & 127;
        g_Wt[j] = Ww[a * HID + h];
    }
}

// ---------------- K1: fp16-acc mma.sync proj GEMM, single A pass -----------
#define SROW 136                      // padded half row stride (272 B)
#define K1_SMEM (2 * 128 * SROW * 2)  // 69632 B -> 3 CTAs/SM

#define MMA_F16ACC(d, a, b) \
    asm volatile("mma.sync.aligned.m16n8k16.row.col.f16.f16.f16.f16 " \
        "{%0,%1}, {%2,%3,%4,%5}, {%6,%7}, {%0,%1};" \
        : "+r"(d[0]), "+r"(d[1]) \
        : "r"(a[0]), "r"(a[1]), "r"(a[2]), "r"(a[3]), "r"(b[0]), "r"(b[1]))

__global__ __launch_bounds__(256, 3) void k1_hmma(const float* __restrict__ emb) {
    extern __shared__ __half sm_[];
    __half* As = sm_;
    __half* Bs = sm_ + 128 * SROW;     // doubles as C staging after compute

    int tid = threadIdx.x;
    int m0 = blockIdx.x * 128;

    for (int i = tid; i < 2048; i += 256) {          // 128 rows x 16 chunks of 8
        int row = i >> 4, k = (i & 15) * 8;
        int gm = m0 + row;
        uint2 p0 = make_uint2(0u, 0u), p1 = make_uint2(0u, 0u);
        if (gm < VOCAB) {
            float4 f0 = *(const float4*)&emb[(size_t)gm * EMB + k];
            float4 f1 = *(const float4*)&emb[(size_t)gm * EMB + k + 4];
            __half2 h0 = __floats2half2_rn(f0.x, f0.y);
            __half2 h1 = __floats2half2_rn(f0.z, f0.w);
            __half2 h2 = __floats2half2_rn(f1.x, f1.y);
            __half2 h3 = __floats2half2_rn(f1.z, f1.w);
            p0 = make_uint2(*(uint32_t*)&h0, *(uint32_t*)&h1);
            p1 = make_uint2(*(uint32_t*)&h2, *(uint32_t*)&h3);
        }
        *(uint2*)&As[row * SROW + k]     = p0;
        *(uint2*)&As[row * SROW + k + 4] = p1;
    }

    int lane = tid & 31, g = lane >> 2, t = lane & 3;
    int wid = tid >> 5;
    int mbase = (wid & 3) * 32;
    int nbase = (wid >> 2) * 64;

    for (int nb = 0; nb < 3; nb++) {
        for (int i = tid; i < 2048; i += 256) {
            int row = i >> 4, k = (i & 15) * 8;
            *(int4*)&Bs[row * SROW + k] =
                *(const int4*)&g_Bf[(nb * 128 + row) * EMB + k];
        }
        __syncthreads();

        uint32_t acc[2][8][2];
#pragma unroll
        for (int mi = 0; mi < 2; mi++)
#pragma unroll
            for (int nj = 0; nj < 8; nj++) { acc[mi][nj][0] = 0u; acc[mi][nj][1] = 0u; }

#pragma unroll
        for (int ks = 0; ks < 8; ks++) {
            int k16 = ks * 16;
            uint32_t a[2][4], b[8][2];
#pragma unroll
            for (int mi = 0; mi < 2; mi++) {
                int r0 = mbase + mi * 16 + g;
                a[mi][0] = *(const uint32_t*)&As[r0 * SROW + k16 + t * 2];
                a[mi][1] = *(const uint32_t*)&As[(r0 + 8) * SROW + k16 + t * 2];
                a[mi][2] = *(const uint32_t*)&As[r0 * SROW + k16 + 8 + t * 2];
                a[mi][3] = *(const uint32_t*)&As[(r0 + 8) * SROW + k16 + 8 + t * 2];
            }
#pragma unroll
            for (int nj = 0; nj < 8; nj++) {
                int n0i = nbase + nj * 8 + g;
                b[nj][0] = *(const uint32_t*)&Bs[n0i * SROW + k16 + t * 2];
                b[nj][1] = *(const uint32_t*)&Bs[n0i * SROW + k16 + 8 + t * 2];
            }
#pragma unroll
            for (int mi = 0; mi < 2; mi++)
#pragma unroll
                for (int nj = 0; nj < 8; nj++) MMA_F16ACC(acc[mi][nj], a[mi], b[nj]);
        }
        __syncthreads();

#pragma unroll
        for (int mi = 0; mi < 2; mi++)
#pragma unroll
            for (int nj = 0; nj < 8; nj++) {
                int r = mbase + mi * 16 + g;
                int cc = nbase + nj * 8 + t * 2;
                *(uint32_t*)&Bs[r * SROW + cc]       = acc[mi][nj][0];
                *(uint32_t*)&Bs[(r + 8) * SROW + cc] = acc[mi][nj][1];
            }
        __syncthreads();
        {
            int row = tid >> 1, seg = tid & 1;
            int gm = m0 + row;
            if (gm < VOCAB) {
                const int4* src = (const int4*)&Bs[row * SROW + seg * 64];
                int4* dst = (int4*)&g_projh[(size_t)gm * HID + nb * 128 + seg * 64];
#pragma unroll
                for (int j = 0; j < 8; j++) dst[j] = src[j];
            }
        }
        __syncthreads();
    }
}

// ---------------- K2: gather + pool + fused scores, 2 inst/block -----------
// 256 blocks x 512 threads. Gather: thread = (f8 = tid&15 -> 8 filters via
// LDG.128, part = (tid>>4)&15 -> 32 tokens, inst = tid>>8). Rolling S-window
// keeps all group addresses in registers so LDGs batch without LDS deps.
#define SPAD 8
__global__ __launch_bounds__(512) void k2_pool(const int* __restrict__ ids_g,
                                               const int* __restrict__ pe1,
                                               const int* __restrict__ pe2,
                                               const float* __restrict__ conv_b,
                                               const float* __restrict__ Wb,
                                               const float* __restrict__ u) {
    int n0 = blockIdx.x * 2;
    int tid = threadIdx.x;
    int f8 = tid & 15, part = (tid >> 4) & 15, inst = tid >> 8;
    __shared__ int S[2][L + 2 + SPAD];
    __shared__ uint4 pb[2][3][16][16];
    __shared__ __align__(16) float Hsm[2][HID];
    __shared__ __align__(16) float partial[2][4][128];
    __shared__ float red[2][4];

    for (int i = tid; i < 2 * L; i += 512) {
        int ii = i >> 9, l = i & 511;
        S[ii][l + 1] = ids_g[(n0 + ii) * L + l] * (HID * 2);
    }
    if (tid < 2) {
        S[tid][0] = 0;
#pragma unroll
        for (int j = 0; j <= SPAD; j++) S[tid][L + 1 + j] = 0;
    }
    __syncthreads();

    int p1 = pe1[n0 + inst], p2 = pe2[n0 + inst];
    int e1 = min(p1, p2), e2 = max(p1, p2);
    e1 = max(0, min(e1, L));
    e2 = max(0, min(e2, L));
    if (e1 == e2) e2 = min(e1 + 1, L);
    int end1 = (e1 > 0) ? e1 : 1;

    __half2 hb[4];
#pragma unroll
    for (int j = 0; j < 4; j++)
        hb[j] = __floats2half2_rn(conv_b[8 * f8 + 2 * j], conv_b[8 * f8 + 2 * j + 1]);
    __half2 zz = __floats2half2_rn(0.f, 0.f);
    __half2 m1[4] = {zz, zz, zz, zz}, m2[4] = {zz, zz, zz, zz}, m3[4] = {zz, zz, zz, zz};

    const char* base = (const char*)g_projh;
    int coff = f8 * 16;
    int t0 = part * 32;
    const int* Si = S[inst];

    // rolling window: sw[j] = S[base + j], j = 0..5 (covers 4 tokens' taps)
    int sw[6];
#pragma unroll
    for (int j = 0; j < 6; j++) sw[j] = Si[t0 + j];

#pragma unroll 2
    for (int bs = t0; bs < t0 + 32; bs += 4) {
        // prefetch next group's S values (reads padded zeros at the tail)
        int sn0 = Si[bs + 6], sn1 = Si[bs + 7], sn2 = Si[bs + 8], sn3 = Si[bs + 9];
#pragma unroll
        for (int j = 0; j < 4; j++) {
            int l = bs + j;
            uint4 v0 = *(const uint4*)(base + sw[j]     + coff);        // tok l-1 tap0
            uint4 v1 = *(const uint4*)(base + sw[j + 1] + 256 + coff);  // tok l   tap1
            uint4 v2 = *(const uint4*)(base + sw[j + 2] + 512 + coff);  // tok l+1 tap2
            __half2 s[4];
            s[0] = __hadd2(__hadd2(*(__half2*)&v0.x, *(__half2*)&v1.x),
                           __hadd2(*(__half2*)&v2.x, hb[0]));
            s[1] = __hadd2(__hadd2(*(__half2*)&v0.y, *(__half2*)&v1.y),
                           __hadd2(*(__half2*)&v2.y, hb[1]));
            s[2] = __hadd2(__hadd2(*(__half2*)&v0.z, *(__half2*)&v1.z),
                           __hadd2(*(__half2*)&v2.z, hb[2]));
            s[3] = __hadd2(__hadd2(*(__half2*)&v0.w, *(__half2*)&v1.w),
                           __hadd2(*(__half2*)&v2.w, hb[3]));
            bool in1 = (l < end1);
            bool in2 = (l >= e1 && l < e2);
            bool in3 = (e2 < L) ? (l >= e2) : (l == L - 1);
#pragma unroll
            for (int q = 0; q < 4; q++) {
                if (in1) m1[q] = __hmax2(m1[q], s[q]);
                if (in2) m2[q] = __hmax2(m2[q], s[q]);
                if (in3) m3[q] = __hmax2(m3[q], s[q]);
            }
        }
        sw[0] = sw[4]; sw[1] = sw[5];
        sw[2] = sn0; sw[3] = sn1; sw[4] = sn2; sw[5] = sn3;
    }
    pb[inst][0][part][f8] = make_uint4(*(uint32_t*)&m1[0], *(uint32_t*)&m1[1],
                                       *(uint32_t*)&m1[2], *(uint32_t*)&m1[3]);
    pb[inst][1][part][f8] = make_uint4(*(uint32_t*)&m2[0], *(uint32_t*)&m2[1],
                                       *(uint32_t*)&m2[2], *(uint32_t*)&m2[3]);
    pb[inst][2][part][f8] = make_uint4(*(uint32_t*)&m3[0], *(uint32_t*)&m3[1],
                                       *(uint32_t*)&m3[2], *(uint32_t*)&m3[3]);
    __syncthreads();

    if (tid < 96) {
        int ii = tid / 48, r = tid % 48;
        int seg = r >> 4, fm = r & 15;
        __half2 r0 = zz, r1 = zz, r2 = zz, r3 = zz;
#pragma unroll
        for (int q = 0; q < 16; q++) {
            uint4 v = pb[ii][seg][q][fm];
            r0 = __hmax2(r0, *(__half2*)&v.x);
            r1 = __hmax2(r1, *(__half2*)&v.y);
            r2 = __hmax2(r2, *(__half2*)&v.z);
            r3 = __hmax2(r3, *(__half2*)&v.w);
        }
        float2 a0 = __half22float2(r0), a1 = __half22float2(r1);
        float2 a2 = __half22float2(r2), a3 = __half22float2(r3);
        float4 hv0 = make_float4(a0.x, a0.y, a1.x, a1.y);
        float4 hv1 = make_float4(a2.x, a2.y, a3.x, a3.y);
        int off = seg * 128 + 8 * fm;
        *(float4*)&g_H[(n0 + ii) * HID + off]     = hv0;
        *(float4*)&g_H[(n0 + ii) * HID + off + 4] = hv1;
        *(float4*)&Hsm[ii][off]     = hv0;
        *(float4*)&Hsm[ii][off + 4] = hv1;
    }
    __syncthreads();

    // ---- fused scores: thread = (a = tid&127, hg = tid>>7 covers 96 h) ----
    {
        int a = tid & 127, hg = tid >> 7;
        float acc0 = 0.f, acc1 = 0.f;
        const float* W = g_Wt + a;
        int h0 = hg * 96;
#pragma unroll 8
        for (int h = h0; h < h0 + 96; h++) {
            float wv = __ldg(W + h * ATT);
            acc0 += Hsm[0][h] * wv;
            acc1 += Hsm[1][h] * wv;
        }
        partial[0][hg][a] = acc0;
        partial[1][hg][a] = acc1;
    }
    __syncthreads();
    if (tid < 256) {
        int ii = tid >> 7, a = tid & 127;
        float s = partial[ii][0][a] + partial[ii][1][a] +
                  partial[ii][2][a] + partial[ii][3][a];
        float e = tanhf(s + __ldg(&Wb[a])) * __ldg(&u[a]);
#pragma unroll
        for (int off = 16; off; off >>= 1)
            e += __shfl_down_sync(0xffffffffu, e, off);
        if ((tid & 31) == 0) red[ii][(tid >> 5) & 3] = e;
    }
    __syncthreads();
    if (tid < 2)
        g_scores[n0 + tid] = red[tid][0] + red[tid][1] + red[tid][2] + red[tid][3];
}

// ---------------- softmax helper (no max subtraction; |s| <= ~9) -----------
__device__ __forceinline__ float block_softmax_512(int tid, float* attn_s,
                                                   float* red16) {
    float e = expf(g_scores[tid]);
    float sv = e;
#pragma unroll
    for (int off = 16; off; off >>= 1)
        sv += __shfl_xor_sync(0xffffffffu, sv, off);
    if ((tid & 31) == 0) red16[tid >> 5] = sv;
    __syncthreads();
    __shared__ float bsum;
    if (tid == 0) {
        float t = 0.f;
        for (int i = 0; i < 16; i++) t += red16[i];
        bsum = t;
    }
    __syncthreads();
    float a = e / bsum;
    attn_s[tid] = a;
    __syncthreads();
    return a;
}

// ---------------- K4: h_bag partials (128 blocks x 4 instances) ------------
__global__ __launch_bounds__(512) void k4_hbag() {
    int tid = threadIdx.x;
    int b = blockIdx.x;
    __shared__ float attn_s[N_INST];
    __shared__ float red16[16];
    block_softmax_512(tid, attn_s, red16);

    if (tid < HID) {
        int n0 = b * 4;
        float acc = 0.f;
#pragma unroll
        for (int j = 0; j < 4; j++)
            acc += attn_s[n0 + j] * g_H[(n0 + j) * HID + tid];
        g_hbp[b * HID + tid] = acc;
    }
}

// ---------------- K5: attn out + hb sum + logits ---------------------------
__global__ __launch_bounds__(512) void k5_out(const float* __restrict__ fc_w,
                                              const float* __restrict__ fc_b,
                                              float* __restrict__ out) {
    int tid = threadIdx.x;
    __shared__ float attn_s[N_INST];
    __shared__ float red16[16];
    __shared__ float hb[HID];

    float a = block_softmax_512(tid, attn_s, red16);
    out[NCLS + tid] = a;

    if (tid < HID) {
        float acc = 0.f;
#pragma unroll 16
        for (int b = 0; b < NHB; b++)
            acc += g_hbp[b * HID + tid];
        hb[tid] = acc;
    }
    __syncthreads();

    int w = tid >> 5, lane = tid & 31;
    for (int t = w; t < NCLS; t += 16) {
        float part = 0.f;
#pragma unroll
        for (int c = lane; c < HID; c += 32)
            part += hb[c] * __ldg(&fc_w[t * HID + c]);
#pragma unroll
        for (int off = 16; off; off >>= 1)
            part += __shfl_down_sync(0xffffffffu, part, off);
        if (lane == 0) out[t] = part + fc_b[t];
    }
}

// ---------------- launch ------------------------------------------------------
extern "C" void kernel_launch(void* const* d_in, const int* in_sizes, int n_in,
                              void* d_out, int out_size) {
    const int*   char_ids = (const int*)d_in[0];
    const int*   pe1      = (const int*)d_in[1];
    const int*   pe2      = (const int*)d_in[2];
    const float* emb      = (const float*)d_in[3];
    const float* conv_w   = (const float*)d_in[4];
    const float* conv_b   = (const float*)d_in[5];
    const float* W_w      = (const float*)d_in[6];
    const float* W_b      = (const float*)d_in[7];
    const float* u_w      = (const float*)d_in[8];
    const float* fc_w     = (const float*)d_in[9];
    const float* fc_b     = (const float*)d_in[10];
    float* out = (float*)d_out;

    static bool attr_set = false;
    if (!attr_set) {
        cudaFuncSetAttribute(k1_hmma, cudaFuncAttributeMaxDynamicSharedMemorySize, K1_SMEM);
        attr_set = true;
    }

    k_prep<<<(2 * HID * EMB + 255) / 256, 256>>>(conv_w, W_w);
    k1_hmma<<<(VOCAB + 127) / 128, 256, K1_SMEM>>>(emb);
    k2_pool<<<N_INST / 2, 512>>>(char_ids, pe1, pe2, conv_b, W_b, u_w);
    k4_hbag<<<NHB, 512>>>();
    k5_out<<<1, 512>>>(fc_w, fc_b, out);
}